// round 1
// baseline (speedup 1.0000x reference)
#include <cuda_runtime.h>
#include <cuda_bf16.h>
#include <cstdint>

// Problem: x [16, 256, 128, 128] f32.
//  1) weight[b,c] = mean over H,W
//  2) idx[b,:] = argsort(weight[b]) ascending, take first 16 (stable)
//  3) out[b,k,:,:] = x[b, idx[b,k], :, :]
//
// HBM-bound: 256 MiB read + 16 MiB read + 16 MiB write ≈ 288 MiB.

#define B 16
#define C 256
#define HW 16384          // 128*128
#define HW4 4096          // HW / 4 (float4 count)
#define K 16

// Scratch (no allocation allowed in kernel_launch)
__device__ float g_weight[B * C];
__device__ int   g_idx[B * K];

// ---------------------------------------------------------------------------
// Kernel 1: per-(b,c) mean over 16384 elements. One block per plane.
// 256 threads x 16 float4 each = 4096 float4 = 64 KB per block.
// ---------------------------------------------------------------------------
__global__ __launch_bounds__(256) void mean_kernel(const float* __restrict__ x) {
    const int bc = blockIdx.x;                       // 0..4095
    const float4* __restrict__ p =
        reinterpret_cast<const float4*>(x + (size_t)bc * HW);

    float s = 0.0f;
    const int t = threadIdx.x;
#pragma unroll
    for (int i = 0; i < 16; ++i) {
        float4 v = __ldg(&p[t + i * 256]);
        s += (v.x + v.y) + (v.z + v.w);
    }

    // warp reduce
#pragma unroll
    for (int off = 16; off > 0; off >>= 1)
        s += __shfl_down_sync(0xFFFFFFFFu, s, off);

    __shared__ float sred[8];
    if ((t & 31) == 0) sred[t >> 5] = s;
    __syncthreads();
    if (t < 8) {
        float v = sred[t];
#pragma unroll
        for (int off = 4; off > 0; off >>= 1)
            v += __shfl_down_sync(0xFFu, v, off);
        if (t == 0) g_weight[bc] = v * (1.0f / (float)HW);
    }
}

// ---------------------------------------------------------------------------
// Kernel 2: per-batch stable rank of 256 channel means; emit bottom-16
// indices in ascending order (matches stable argsort + slice).
// ---------------------------------------------------------------------------
__global__ __launch_bounds__(256) void select_kernel() {
    const int b = blockIdx.x;
    const int c = threadIdx.x;
    __shared__ float sw[C];
    const float v = g_weight[b * C + c];
    sw[c] = v;
    __syncthreads();

    int rank = 0;
#pragma unroll 8
    for (int j = 0; j < C; ++j) {
        const float u = sw[j];
        rank += (u < v) || (u == v && j < c);
    }
    if (rank < K) g_idx[b * K + rank] = c;
}

// ---------------------------------------------------------------------------
// Kernel 3: gather selected planes. blockIdx.x = output plane (b*16+k),
// blockIdx.y = split within the plane. float4 copy.
// ---------------------------------------------------------------------------
__global__ __launch_bounds__(256) void gather_kernel(const float* __restrict__ x,
                                                     float* __restrict__ out) {
    const int plane = blockIdx.x;                    // 0..255
    const int b = plane >> 4;
    const int c = g_idx[plane];

    const float4* __restrict__ src =
        reinterpret_cast<const float4*>(x + ((size_t)b * C + c) * HW);
    float4* __restrict__ dst =
        reinterpret_cast<float4*>(out + (size_t)plane * HW);

    const int stride = blockDim.x * gridDim.y;       // 256 * 4 = 1024
    for (int i = threadIdx.x + blockIdx.y * blockDim.x; i < HW4; i += stride)
        dst[i] = __ldg(&src[i]);
}

// ---------------------------------------------------------------------------
extern "C" void kernel_launch(void* const* d_in, const int* in_sizes, int n_in,
                              void* d_out, int out_size) {
    const float* x = (const float*)d_in[0];
    float* out = (float*)d_out;

    mean_kernel<<<B * C, 256>>>(x);
    select_kernel<<<B, 256>>>();
    gather_kernel<<<dim3(B * K, 4), 256>>>(x, out);
}